// round 2
// baseline (speedup 1.0000x reference)
#include <cuda_runtime.h>
#include <math.h>

#define T_TOK 2048
#define DDIM  2048
#define FDIM  4096
#define NEXP  8

#define BM 64
#define BN 64
#define BK 16
#define NTHREADS 128

// ---- static scratch (no allocations allowed) ----
__device__ int   g_count[NEXP];
__device__ int   g_list[NEXP * T_TOK];
__device__ int   g_eidx[T_TOK];
__device__ float g_wgt[T_TOK];
__device__ float g_h[(size_t)T_TOK * FDIM];   // [T, F] intermediate

__global__ void zero_counts() {
    if (threadIdx.x < NEXP) g_count[threadIdx.x] = 0;
}

// one warp per token: logits = x[t] @ rw, top-1 + sigmoid
__global__ void router_kernel(const float* __restrict__ x,
                              const float* __restrict__ rw) {
    int t = blockIdx.x * blockDim.y + threadIdx.y;
    if (t >= T_TOK) return;
    int lane = threadIdx.x;
    float acc[NEXP];
#pragma unroll
    for (int e = 0; e < NEXP; e++) acc[e] = 0.f;
    const float* xr = x + (size_t)t * DDIM;
    for (int d = lane; d < DDIM; d += 32) {
        float xv = xr[d];
        const float4* r = (const float4*)(rw + (size_t)d * NEXP);
        float4 r0 = r[0], r1 = r[1];
        acc[0] += xv * r0.x; acc[1] += xv * r0.y;
        acc[2] += xv * r0.z; acc[3] += xv * r0.w;
        acc[4] += xv * r1.x; acc[5] += xv * r1.y;
        acc[6] += xv * r1.z; acc[7] += xv * r1.w;
    }
#pragma unroll
    for (int off = 16; off > 0; off >>= 1) {
#pragma unroll
        for (int e = 0; e < NEXP; e++)
            acc[e] += __shfl_down_sync(0xffffffffu, acc[e], off);
    }
    if (lane == 0) {
        int best = 0; float bv = acc[0];
#pragma unroll
        for (int e = 1; e < NEXP; e++)
            if (acc[e] > bv) { bv = acc[e]; best = e; }
        g_eidx[t] = best;
        g_wgt[t]  = 1.f / (1.f + expf(-bv));
    }
}

__global__ void scatter_kernel() {
    int t = blockIdx.x * blockDim.x + threadIdx.x;
    if (t < T_TOK) {
        int e = g_eidx[t];
        int p = atomicAdd(&g_count[e], 1);
        g_list[e * T_TOK + p] = t;
    }
}

__device__ __forceinline__ float silu_f(float g) {
    return g / (1.f + expf(-g));
}

// h[tok, n] = silu(x[tok] @ Wg[:,n]) * (x[tok] @ Wu[:,n]) for tokens of expert e
template<bool SHARED>
__global__ void __launch_bounds__(NTHREADS)
gateup_kernel(const float* __restrict__ x,
              const float* __restrict__ wg,
              const float* __restrict__ wu) {
    int e   = SHARED ? 0 : blockIdx.z;
    int cnt = SHARED ? T_TOK : g_count[e];
    int m0  = blockIdx.y * BM;
    if (m0 >= cnt) return;
    int n0  = blockIdx.x * BN;
    const float* wgb = wg + (SHARED ? 0 : (size_t)e * DDIM * FDIM);
    const float* wub = wu + (SHARED ? 0 : (size_t)e * DDIM * FDIM);

    __shared__ float As[BK][BM + 4];
    __shared__ float Bg[BK][BN];
    __shared__ float Bu[BK][BN];
    __shared__ int   toks[BM];

    int tid = threadIdx.x;
    if (tid < BM) {
        int m = m0 + tid;
        toks[tid] = (m < cnt) ? (SHARED ? m : g_list[e * T_TOK + m]) : -1;
    }
    __syncthreads();

    float accg[8][4], accu[8][4];
#pragma unroll
    for (int i = 0; i < 8; i++)
#pragma unroll
        for (int j = 0; j < 4; j++) { accg[i][j] = 0.f; accu[i][j] = 0.f; }

    int tr = tid >> 4;   // 0..7 -> rows tr*8..tr*8+7
    int tc = tid & 15;   // 0..15 -> cols tc*4..tc*4+3

    for (int k0 = 0; k0 < DDIM; k0 += BK) {
        // A tile: 64 rows x 16 k, gathered by token id, stored transposed
#pragma unroll
        for (int it = 0; it < 2; it++) {
            int s   = tid * 2 + it;      // 0..255 float4 slots
            int row = s >> 2;            // 0..63
            int q   = s & 3;             // 0..3 (quad of 4 floats)
            int tk  = toks[row];
            float4 v = make_float4(0.f, 0.f, 0.f, 0.f);
            if (tk >= 0)
                v = *(const float4*)(x + (size_t)tk * DDIM + k0 + q * 4);
            As[q * 4 + 0][row] = v.x; As[q * 4 + 1][row] = v.y;
            As[q * 4 + 2][row] = v.z; As[q * 4 + 3][row] = v.w;
        }
        // B tiles: 16 k-rows x 64 n
#pragma unroll
        for (int it = 0; it < 2; it++) {
            int s  = tid * 2 + it;
            int kr = s >> 4;             // 0..15
            int q  = s & 15;             // 0..15
            size_t off = (size_t)(k0 + kr) * FDIM + n0 + q * 4;
            *(float4*)&Bg[kr][q * 4] = *(const float4*)(wgb + off);
            *(float4*)&Bu[kr][q * 4] = *(const float4*)(wub + off);
        }
        __syncthreads();
#pragma unroll
        for (int k = 0; k < BK; k++) {
            float a[8];
            *(float4*)&a[0] = *(const float4*)&As[k][tr * 8];
            *(float4*)&a[4] = *(const float4*)&As[k][tr * 8 + 4];
            float4 bg = *(const float4*)&Bg[k][tc * 4];
            float4 bu = *(const float4*)&Bu[k][tc * 4];
#pragma unroll
            for (int i = 0; i < 8; i++) {
                accg[i][0] += a[i] * bg.x; accg[i][1] += a[i] * bg.y;
                accg[i][2] += a[i] * bg.z; accg[i][3] += a[i] * bg.w;
                accu[i][0] += a[i] * bu.x; accu[i][1] += a[i] * bu.y;
                accu[i][2] += a[i] * bu.z; accu[i][3] += a[i] * bu.w;
            }
        }
        __syncthreads();
    }

#pragma unroll
    for (int i = 0; i < 8; i++) {
        int tk = toks[tr * 8 + i];
        if (tk < 0) continue;
        float4 o;
        o.x = silu_f(accg[i][0]) * accu[i][0];
        o.y = silu_f(accg[i][1]) * accu[i][1];
        o.z = silu_f(accg[i][2]) * accu[i][2];
        o.w = silu_f(accg[i][3]) * accu[i][3];
        *(float4*)(g_h + (size_t)tk * FDIM + n0 + tc * 4) = o;
    }
}

// out[tok, n] (+)= wgt * (h[tok] @ Wd[:, n])
template<bool SHARED>
__global__ void __launch_bounds__(NTHREADS)
down_kernel(const float* __restrict__ wd, float* __restrict__ out) {
    int e   = SHARED ? 0 : blockIdx.z;
    int cnt = SHARED ? T_TOK : g_count[e];
    int m0  = blockIdx.y * BM;
    if (m0 >= cnt) return;
    int n0  = blockIdx.x * BN;
    const float* wdb = wd + (SHARED ? 0 : (size_t)e * FDIM * DDIM);

    __shared__ float As[BK][BM + 4];
    __shared__ float Bs[BK][BN];
    __shared__ int   toks[BM];

    int tid = threadIdx.x;
    if (tid < BM) {
        int m = m0 + tid;
        toks[tid] = (m < cnt) ? (SHARED ? m : g_list[e * T_TOK + m]) : -1;
    }
    __syncthreads();

    float acc[8][4];
#pragma unroll
    for (int i = 0; i < 8; i++)
#pragma unroll
        for (int j = 0; j < 4; j++) acc[i][j] = 0.f;

    int tr = tid >> 4;
    int tc = tid & 15;

    for (int k0 = 0; k0 < FDIM; k0 += BK) {
#pragma unroll
        for (int it = 0; it < 2; it++) {
            int s   = tid * 2 + it;
            int row = s >> 2;
            int q   = s & 3;
            int tk  = toks[row];
            float4 v = make_float4(0.f, 0.f, 0.f, 0.f);
            if (tk >= 0)
                v = *(const float4*)(g_h + (size_t)tk * FDIM + k0 + q * 4);
            As[q * 4 + 0][row] = v.x; As[q * 4 + 1][row] = v.y;
            As[q * 4 + 2][row] = v.z; As[q * 4 + 3][row] = v.w;
        }
#pragma unroll
        for (int it = 0; it < 2; it++) {
            int s  = tid * 2 + it;
            int kr = s >> 4;
            int q  = s & 15;
            size_t off = (size_t)(k0 + kr) * DDIM + n0 + q * 4;
            *(float4*)&Bs[kr][q * 4] = *(const float4*)(wdb + off);
        }
        __syncthreads();
#pragma unroll
        for (int k = 0; k < BK; k++) {
            float a[8];
            *(float4*)&a[0] = *(const float4*)&As[k][tr * 8];
            *(float4*)&a[4] = *(const float4*)&As[k][tr * 8 + 4];
            float4 b = *(const float4*)&Bs[k][tc * 4];
#pragma unroll
            for (int i = 0; i < 8; i++) {
                acc[i][0] += a[i] * b.x; acc[i][1] += a[i] * b.y;
                acc[i][2] += a[i] * b.z; acc[i][3] += a[i] * b.w;
            }
        }
        __syncthreads();
    }

#pragma unroll
    for (int i = 0; i < 8; i++) {
        int tk = toks[tr * 8 + i];
        if (tk < 0) continue;
        float s = SHARED ? 1.f : g_wgt[tk];
        float* op = out + (size_t)tk * DDIM + n0 + tc * 4;
        float4 o;
        o.x = s * acc[i][0]; o.y = s * acc[i][1];
        o.z = s * acc[i][2]; o.w = s * acc[i][3];
        if (SHARED) {
            float4 p = *(float4*)op;
            o.x += p.x; o.y += p.y; o.z += p.z; o.w += p.w;
        }
        *(float4*)op = o;
    }
}

extern "C" void kernel_launch(void* const* d_in, const int* in_sizes, int n_in,
                              void* d_out, int out_size) {
    const float* x   = (const float*)d_in[0];
    const float* rw  = (const float*)d_in[1];
    const float* wg  = (const float*)d_in[2];
    const float* wu  = (const float*)d_in[3];
    const float* wd  = (const float*)d_in[4];
    const float* wsg = (const float*)d_in[5];
    const float* wsu = (const float*)d_in[6];
    const float* wsd = (const float*)d_in[7];
    float* out = (float*)d_out;

    zero_counts<<<1, 32>>>();
    router_kernel<<<T_TOK / 8, dim3(32, 8)>>>(x, rw);
    scatter_kernel<<<T_TOK / 256, 256>>>();

    // routed experts: gate/up -> h, then down -> out (writes every token once)
    dim3 g1(FDIM / BN, T_TOK / BM, NEXP);
    gateup_kernel<false><<<g1, NTHREADS>>>(x, wg, wu);
    dim3 g2(DDIM / BN, T_TOK / BM, NEXP);
    down_kernel<false><<<g2, NTHREADS>>>(wd, out);

    // shared expert: gate/up -> h (reuse), then down += out
    dim3 g3(FDIM / BN, T_TOK / BM, 1);
    gateup_kernel<true><<<g3, NTHREADS>>>(x, wsg, wsu);
    dim3 g4(DDIM / BN, T_TOK / BM, 1);
    down_kernel<true><<<g4, NTHREADS>>>(wsd, out);
}

// round 5
// speedup vs baseline: 1.2494x; 1.2494x over previous
#include <cuda_runtime.h>
#include <math.h>
#include <stdint.h>

#define T_TOK 2048
#define DDIM  2048
#define FDIM  4096
#define NEXP  8

#define AS_STRIDE 36     // 128 rows x 32 cols, padded
#define BS_STRIDE_GU 136 // 32 rows x 128 cols
#define BS_STRIDE_DN 72  // 32 rows x 64 cols
#define NSTG 3

#define A_TILE_FLTS (128 * AS_STRIDE)
#define BGU_TILE_FLTS (32 * BS_STRIDE_GU)
#define BDN_TILE_FLTS (32 * BS_STRIDE_DN)
#define STAGE_GU (A_TILE_FLTS + BGU_TILE_FLTS)
#define STAGE_DN (A_TILE_FLTS + BDN_TILE_FLTS)
#define SMEM_GU (NSTG * STAGE_GU * 4)
#define SMEM_DN (NSTG * STAGE_DN * 4)

// ---- static scratch ----
__device__ int   g_cnt[NEXP];
__device__ int   g_eid[T_TOK];
__device__ float g_w[T_TOK];
__device__ int   g_list[NEXP * T_TOK];
__device__ float g_h[(size_t)T_TOK * FDIM];
__device__ float g_hs[(size_t)T_TOK * FDIM];

// ---- helpers ----
__device__ __forceinline__ uint32_t smem_u32(const void* p) {
    uint32_t a;
    asm("{ .reg .u64 t; cvta.to.shared.u64 t, %1; cvt.u32.u64 %0, t; }"
        : "=r"(a) : "l"(p));
    return a;
}

__device__ __forceinline__ void cpa16(uint32_t dst, const float* src, int srcsz) {
    asm volatile("cp.async.cg.shared.global [%0], [%1], 16, %2;"
                 :: "r"(dst), "l"(src), "r"(srcsz) : "memory");
}
#define CP_COMMIT() asm volatile("cp.async.commit_group;" ::: "memory")
#define CP_WAIT1()  asm volatile("cp.async.wait_group 1;" ::: "memory")

#define MMA_TF32(d, a, b) \
    asm volatile("mma.sync.aligned.m16n8k8.row.col.f32.tf32.tf32.f32 " \
        "{%0,%1,%2,%3}, {%4,%5,%6,%7}, {%8,%9}, {%0,%1,%2,%3};" \
        : "+f"((d)[0]), "+f"((d)[1]), "+f"((d)[2]), "+f"((d)[3]) \
        : "r"((a)[0]), "r"((a)[1]), "r"((a)[2]), "r"((a)[3]), \
          "r"((b)[0]), "r"((b)[1]))

// round-to-nearest tf32; result is an fp32 bit pattern with low mantissa zeroed
__device__ __forceinline__ uint32_t cvt_tf32(float f) {
    uint32_t u;
    asm("cvt.rna.tf32.f32 %0, %1;" : "=r"(u) : "f"(f));
    return u;
}
// split f into hi (tf32-exact) and lo (residual, fp32 bits; HW truncation of lo is 2^-22-scale)
__device__ __forceinline__ void tf32_split(float f, uint32_t& hi, uint32_t& lo) {
    hi = cvt_tf32(f);
    lo = __float_as_uint(f - __uint_as_float(hi));
}

__device__ __forceinline__ float silu_f(float g) {
    return g / (1.f + __expf(-g));
}

// ---- routing ----
__global__ void zero_counts() {
    if (threadIdx.x < NEXP) g_cnt[threadIdx.x] = 0;
}

__global__ void router_kernel(const float* __restrict__ x,
                              const float* __restrict__ rw) {
    int t = blockIdx.x * blockDim.y + threadIdx.y;
    if (t >= T_TOK) return;
    int lane = threadIdx.x;
    float acc[NEXP];
#pragma unroll
    for (int e = 0; e < NEXP; e++) acc[e] = 0.f;
    const float* xr = x + (size_t)t * DDIM;
    for (int d = lane; d < DDIM; d += 32) {
        float xv = xr[d];
        const float4* r = (const float4*)(rw + (size_t)d * NEXP);
        float4 r0 = r[0], r1 = r[1];
        acc[0] += xv * r0.x; acc[1] += xv * r0.y;
        acc[2] += xv * r0.z; acc[3] += xv * r0.w;
        acc[4] += xv * r1.x; acc[5] += xv * r1.y;
        acc[6] += xv * r1.z; acc[7] += xv * r1.w;
    }
#pragma unroll
    for (int off = 16; off > 0; off >>= 1)
#pragma unroll
        for (int e = 0; e < NEXP; e++)
            acc[e] += __shfl_down_sync(0xffffffffu, acc[e], off);
    if (lane == 0) {
        int best = 0; float bv = acc[0];
#pragma unroll
        for (int e = 1; e < NEXP; e++)
            if (acc[e] > bv) { bv = acc[e]; best = e; }
        g_eid[t] = best;
        g_w[t]   = 1.f / (1.f + expf(-bv));
    }
}

__global__ void scatter_kernel() {
    int t = blockIdx.x * blockDim.x + threadIdx.x;
    if (t < T_TOK) {
        int e = g_eid[t];
        int p = atomicAdd(&g_cnt[e], 1);
        g_list[e * T_TOK + p] = t;
    }
}

// ================= gate+up GEMM =================
template<bool SHARED>
__global__ void __launch_bounds__(256)
gu_kernel(const float* __restrict__ x,
          const float* __restrict__ wgA,
          const float* __restrict__ wuA,
          float* __restrict__ hout) {
    int e   = SHARED ? 0 : blockIdx.z;
    int cnt = SHARED ? T_TOK : g_cnt[e];
    int m0  = blockIdx.y * 128;
    if (m0 >= cnt) return;
    int n0  = blockIdx.x * 64;
    const float* wg = wgA + (SHARED ? 0 : (size_t)e * DDIM * FDIM);
    const float* wu = wuA + (SHARED ? 0 : (size_t)e * DDIM * FDIM);

    extern __shared__ float sm[];
    __shared__ int toks[128];
    int tid = threadIdx.x;
    if (tid < 128) {
        int m = m0 + tid;
        toks[tid] = (m < cnt) ? (SHARED ? m : g_list[e * T_TOK + m]) : -1;
    }
    __syncthreads();

    uint32_t smb = smem_u32(sm);

    const float* asrc[4];
    int apred[4];
    uint32_t adst[4];
#pragma unroll
    for (int i = 0; i < 4; i++) {
        int s = tid + 256 * i;
        int row = s >> 3, chk = s & 7;
        int tk = toks[row];
        apred[i] = (tk >= 0) ? 16 : 0;
        asrc[i]  = x + ((tk >= 0) ? ((size_t)tk * DDIM + chk * 4) : 0);
        adst[i]  = (row * AS_STRIDE + chk * 4) * 4;
    }
    const float* bsrc[4];
    uint32_t bdst[4];
#pragma unroll
    for (int i = 0; i < 4; i++) {
        int s = tid + 256 * i;
        int row = s >> 5, chk = s & 31;
        const float* base = (chk < 16) ? (wg + n0 + chk * 4)
                                       : (wu + n0 + (chk - 16) * 4);
        bsrc[i] = base + (size_t)row * FDIM;
        bdst[i] = (A_TILE_FLTS + row * BS_STRIDE_GU + chk * 4) * 4;
    }

    auto load_stage = [&](int kc, int st) {
        uint32_t sb = smb + st * STAGE_GU * 4;
        int k0 = kc * 32;
#pragma unroll
        for (int i = 0; i < 4; i++) cpa16(sb + adst[i], asrc[i] + k0, apred[i]);
#pragma unroll
        for (int i = 0; i < 4; i++) cpa16(sb + bdst[i], bsrc[i] + (size_t)k0 * FDIM, 16);
        CP_COMMIT();
    };

    int wid = tid >> 5, lane = tid & 31;
    int wm = (wid >> 1) * 32;
    int wn = (wid & 1) * 32;
    int gr = lane >> 2, gc = lane & 3;

    float acc[2][8][4];
#pragma unroll
    for (int mt = 0; mt < 2; mt++)
#pragma unroll
        for (int nt = 0; nt < 8; nt++)
#pragma unroll
            for (int j = 0; j < 4; j++) acc[mt][nt][j] = 0.f;

    const int NKC = DDIM / 32;  // 64
    load_stage(0, 0);
    load_stage(1, 1);

    for (int kc = 0; kc < NKC; kc++) {
        CP_WAIT1();
        __syncthreads();
        if (kc + 2 < NKC) load_stage(kc + 2, (kc + 2) % NSTG);

        const float* As = sm + (kc % NSTG) * STAGE_GU;
        const float* Bs = As + A_TILE_FLTS;
#pragma unroll
        for (int ks = 0; ks < 4; ks++) {
            uint32_t a_hi[2][4], a_lo[2][4];
#pragma unroll
            for (int mt = 0; mt < 2; mt++) {
                const float* ap = As + (wm + mt * 16 + gr) * AS_STRIDE + ks * 8 + gc;
                tf32_split(ap[0],                 a_hi[mt][0], a_lo[mt][0]);
                tf32_split(ap[8 * AS_STRIDE],     a_hi[mt][1], a_lo[mt][1]);
                tf32_split(ap[4],                 a_hi[mt][2], a_lo[mt][2]);
                tf32_split(ap[8 * AS_STRIDE + 4], a_hi[mt][3], a_lo[mt][3]);
            }
#pragma unroll
            for (int nt = 0; nt < 8; nt++) {
                int col = (nt < 4) ? (wn + nt * 8) : (64 + wn + (nt - 4) * 8);
                const float* bp = Bs + (ks * 8 + gc) * BS_STRIDE_GU + col + gr;
                uint32_t b_hi[2], b_lo[2];
                tf32_split(bp[0],                  b_hi[0], b_lo[0]);
                tf32_split(bp[4 * BS_STRIDE_GU],   b_hi[1], b_lo[1]);
#pragma unroll
                for (int mt = 0; mt < 2; mt++) {
                    MMA_TF32(acc[mt][nt], a_hi[mt], b_lo);
                    MMA_TF32(acc[mt][nt], a_lo[mt], b_hi);
                    MMA_TF32(acc[mt][nt], a_hi[mt], b_hi);
                }
            }
        }
        __syncthreads();
    }

#pragma unroll
    for (int mt = 0; mt < 2; mt++) {
#pragma unroll
        for (int half = 0; half < 2; half++) {
            int row = wm + mt * 16 + gr + half * 8;
            int tk = toks[row];
            if (tk < 0) continue;
            float* orow = hout + (size_t)tk * FDIM + n0 + wn;
#pragma unroll
            for (int nt = 0; nt < 4; nt++) {
                float gg0 = acc[mt][nt][half * 2 + 0];
                float gg1 = acc[mt][nt][half * 2 + 1];
                float uu0 = acc[mt][nt + 4][half * 2 + 0];
                float uu1 = acc[mt][nt + 4][half * 2 + 1];
                float2 v;
                v.x = silu_f(gg0) * uu0;
                v.y = silu_f(gg1) * uu1;
                *(float2*)(orow + nt * 8 + gc * 2) = v;
            }
        }
    }
}

// ================= down GEMM =================
template<bool SHARED>
__global__ void __launch_bounds__(256)
dn_kernel(const float* __restrict__ hin,
          const float* __restrict__ wdA,
          float* __restrict__ out) {
    int e   = SHARED ? 0 : blockIdx.z;
    int cnt = SHARED ? T_TOK : g_cnt[e];
    int m0  = blockIdx.y * 128;
    if (m0 >= cnt) return;
    int n0  = blockIdx.x * 64;
    const float* wd = wdA + (SHARED ? 0 : (size_t)e * FDIM * DDIM);

    extern __shared__ float sm[];
    __shared__ int toks[128];
    int tid = threadIdx.x;
    if (tid < 128) {
        int m = m0 + tid;
        toks[tid] = (m < cnt) ? (SHARED ? m : g_list[e * T_TOK + m]) : -1;
    }
    __syncthreads();

    uint32_t smb = smem_u32(sm);

    const float* asrc[4];
    int apred[4];
    uint32_t adst[4];
#pragma unroll
    for (int i = 0; i < 4; i++) {
        int s = tid + 256 * i;
        int row = s >> 3, chk = s & 7;
        int tk = toks[row];
        apred[i] = (tk >= 0) ? 16 : 0;
        asrc[i]  = hin + ((tk >= 0) ? ((size_t)tk * FDIM + chk * 4) : 0);
        adst[i]  = (row * AS_STRIDE + chk * 4) * 4;
    }
    const float* bsrc[2];
    uint32_t bdst[2];
#pragma unroll
    for (int i = 0; i < 2; i++) {
        int s = tid + 256 * i;
        int row = s >> 4, chk = s & 15;
        bsrc[i] = wd + (size_t)row * DDIM + n0 + chk * 4;
        bdst[i] = (A_TILE_FLTS + row * BS_STRIDE_DN + chk * 4) * 4;
    }

    auto load_stage = [&](int kc, int st) {
        uint32_t sb = smb + st * STAGE_DN * 4;
        int k0 = kc * 32;
#pragma unroll
        for (int i = 0; i < 4; i++) cpa16(sb + adst[i], asrc[i] + k0, apred[i]);
#pragma unroll
        for (int i = 0; i < 2; i++) cpa16(sb + bdst[i], bsrc[i] + (size_t)k0 * DDIM, 16);
        CP_COMMIT();
    };

    int wid = tid >> 5, lane = tid & 31;
    int wm = (wid >> 1) * 32;
    int wn = (wid & 1) * 32;
    int gr = lane >> 2, gc = lane & 3;

    float acc[2][4][4];
#pragma unroll
    for (int mt = 0; mt < 2; mt++)
#pragma unroll
        for (int nt = 0; nt < 4; nt++)
#pragma unroll
            for (int j = 0; j < 4; j++) acc[mt][nt][j] = 0.f;

    const int NKC = FDIM / 32;  // 128
    load_stage(0, 0);
    load_stage(1, 1);

    for (int kc = 0; kc < NKC; kc++) {
        CP_WAIT1();
        __syncthreads();
        if (kc + 2 < NKC) load_stage(kc + 2, (kc + 2) % NSTG);

        const float* As = sm + (kc % NSTG) * STAGE_DN;
        const float* Bs = As + A_TILE_FLTS;
#pragma unroll
        for (int ks = 0; ks < 4; ks++) {
            uint32_t a_hi[2][4], a_lo[2][4];
#pragma unroll
            for (int mt = 0; mt < 2; mt++) {
                const float* ap = As + (wm + mt * 16 + gr) * AS_STRIDE + ks * 8 + gc;
                tf32_split(ap[0],                 a_hi[mt][0], a_lo[mt][0]);
                tf32_split(ap[8 * AS_STRIDE],     a_hi[mt][1], a_lo[mt][1]);
                tf32_split(ap[4],                 a_hi[mt][2], a_lo[mt][2]);
                tf32_split(ap[8 * AS_STRIDE + 4], a_hi[mt][3], a_lo[mt][3]);
            }
#pragma unroll
            for (int nt = 0; nt < 4; nt++) {
                const float* bp = Bs + (ks * 8 + gc) * BS_STRIDE_DN + wn + nt * 8 + gr;
                uint32_t b_hi[2], b_lo[2];
                tf32_split(bp[0],                b_hi[0], b_lo[0]);
                tf32_split(bp[4 * BS_STRIDE_DN], b_hi[1], b_lo[1]);
#pragma unroll
                for (int mt = 0; mt < 2; mt++) {
                    MMA_TF32(acc[mt][nt], a_hi[mt], b_lo);
                    MMA_TF32(acc[mt][nt], a_lo[mt], b_hi);
                    MMA_TF32(acc[mt][nt], a_hi[mt], b_hi);
                }
            }
        }
        __syncthreads();
    }

#pragma unroll
    for (int mt = 0; mt < 2; mt++) {
#pragma unroll
        for (int half = 0; half < 2; half++) {
            int row = wm + mt * 16 + gr + half * 8;
            int tk = toks[row];
            if (tk < 0) continue;
            float wt = SHARED ? 1.f : g_w[tk];
            float* orow = out + (size_t)tk * DDIM + n0 + wn;
#pragma unroll
            for (int nt = 0; nt < 4; nt++) {
                float2 v;
                v.x = wt * acc[mt][nt][half * 2 + 0];
                v.y = wt * acc[mt][nt][half * 2 + 1];
                float* op = orow + nt * 8 + gc * 2;
                if (SHARED) {
                    float2 p = *(float2*)op;
                    v.x += p.x; v.y += p.y;
                }
                *(float2*)op = v;
            }
        }
    }
}

// ================= host =================
extern "C" void kernel_launch(void* const* d_in, const int* in_sizes, int n_in,
                              void* d_out, int out_size) {
    const float* x   = (const float*)d_in[0];
    const float* rw  = (const float*)d_in[1];
    const float* wg  = (const float*)d_in[2];
    const float* wu  = (const float*)d_in[3];
    const float* wd  = (const float*)d_in[4];
    const float* wsg = (const float*)d_in[5];
    const float* wsu = (const float*)d_in[6];
    const float* wsd = (const float*)d_in[7];
    float* out = (float*)d_out;

    void *p_h = 0, *p_hs = 0;
    cudaGetSymbolAddress(&p_h, g_h);
    cudaGetSymbolAddress(&p_hs, g_hs);

    cudaFuncSetAttribute(gu_kernel<false>, cudaFuncAttributeMaxDynamicSharedMemorySize, SMEM_GU);
    cudaFuncSetAttribute(gu_kernel<true>,  cudaFuncAttributeMaxDynamicSharedMemorySize, SMEM_GU);
    cudaFuncSetAttribute(dn_kernel<false>, cudaFuncAttributeMaxDynamicSharedMemorySize, SMEM_DN);
    cudaFuncSetAttribute(dn_kernel<true>,  cudaFuncAttributeMaxDynamicSharedMemorySize, SMEM_DN);

    zero_counts<<<1, 32>>>();
    router_kernel<<<T_TOK / 8, dim3(32, 8)>>>(x, rw);
    scatter_kernel<<<T_TOK / 256, 256>>>();

    gu_kernel<false><<<dim3(FDIM / 64, T_TOK / 128, NEXP), 256, SMEM_GU>>>(x, wg, wu, (float*)p_h);
    dn_kernel<false><<<dim3(DDIM / 64, T_TOK / 128, NEXP), 256, SMEM_DN>>>((const float*)p_h, wd, out);

    gu_kernel<true><<<dim3(FDIM / 64, T_TOK / 128, 1), 256, SMEM_GU>>>(x, wsg, wsu, (float*)p_hs);
    dn_kernel<true><<<dim3(DDIM / 64, T_TOK / 128, 1), 256, SMEM_DN>>>((const float*)p_hs, wsd, out);
}

// round 6
// speedup vs baseline: 1.8592x; 1.4881x over previous
#include <cuda_runtime.h>
#include <math.h>
#include <stdint.h>

#define T_TOK 2048
#define DDIM  2048
#define FDIM  4096
#define NEXP  8

#define AS_STRIDE 36     // 128 rows x 32 cols, padded
#define BS_STRIDE_GU 136 // 32 rows x 128 cols
#define BS_STRIDE_DN 72  // 32 rows x 64 cols
#define NSTG 3

#define A_TILE_FLTS (128 * AS_STRIDE)
#define BGU_TILE_FLTS (32 * BS_STRIDE_GU)
#define BDN_TILE_FLTS (32 * BS_STRIDE_DN)
#define STAGE_GU (A_TILE_FLTS + BGU_TILE_FLTS)
#define STAGE_DN (A_TILE_FLTS + BDN_TILE_FLTS)
#define SMEM_GU (NSTG * STAGE_GU * 4)
#define SMEM_DN (NSTG * STAGE_DN * 4)

// ---- static scratch ----
__device__ int   g_cnt[NEXP];
__device__ int   g_eid[T_TOK];
__device__ float g_w[T_TOK];
__device__ int   g_list[NEXP * T_TOK];
__device__ float g_h[(size_t)T_TOK * FDIM];
__device__ float g_hs[(size_t)T_TOK * FDIM];

// ---- helpers ----
__device__ __forceinline__ uint32_t smem_u32(const void* p) {
    uint32_t a;
    asm("{ .reg .u64 t; cvta.to.shared.u64 t, %1; cvt.u32.u64 %0, t; }"
        : "=r"(a) : "l"(p));
    return a;
}

__device__ __forceinline__ void cpa16(uint32_t dst, const float* src, int srcsz) {
    asm volatile("cp.async.cg.shared.global [%0], [%1], 16, %2;"
                 :: "r"(dst), "l"(src), "r"(srcsz) : "memory");
}
#define CP_COMMIT() asm volatile("cp.async.commit_group;" ::: "memory")
#define CP_WAIT1()  asm volatile("cp.async.wait_group 1;" ::: "memory")

// bf16 m16n8k16 MMA: A = 4 b32 (8 bf16), B = 2 b32 (4 bf16), C/D = 4 f32
#define MMA_BF16(d, a, b) \
    asm volatile("mma.sync.aligned.m16n8k16.row.col.f32.bf16.bf16.f32 " \
        "{%0,%1,%2,%3}, {%4,%5,%6,%7}, {%8,%9}, {%0,%1,%2,%3};" \
        : "+f"((d)[0]), "+f"((d)[1]), "+f"((d)[2]), "+f"((d)[3]) \
        : "r"((a)[0]), "r"((a)[1]), "r"((a)[2]), "r"((a)[3]), \
          "r"((b)[0]), "r"((b)[1]))

// split float2 (f.x = k even -> lower half, f.y = k odd -> upper half)
// into hi bf16x2 and lo (residual) bf16x2
__device__ __forceinline__ void bf16_split2(float2 f, uint32_t& hi, uint32_t& lo) {
    uint32_t h;
    asm("cvt.rn.bf16x2.f32 %0, %1, %2;" : "=r"(h) : "f"(f.y), "f"(f.x));
    float hx = __uint_as_float(h << 16);           // lower half -> f32
    float hy = __uint_as_float(h & 0xffff0000u);   // upper half -> f32
    asm("cvt.rn.bf16x2.f32 %0, %1, %2;" : "=r"(lo) : "f"(f.y - hy), "f"(f.x - hx));
    hi = h;
}

__device__ __forceinline__ float silu_f(float g) {
    return g / (1.f + __expf(-g));
}

// ---- routing ----
__global__ void zero_counts() {
    if (threadIdx.x < NEXP) g_cnt[threadIdx.x] = 0;
}

__global__ void router_kernel(const float* __restrict__ x,
                              const float* __restrict__ rw) {
    int t = blockIdx.x * blockDim.y + threadIdx.y;
    if (t >= T_TOK) return;
    int lane = threadIdx.x;
    float acc[NEXP];
#pragma unroll
    for (int e = 0; e < NEXP; e++) acc[e] = 0.f;
    const float* xr = x + (size_t)t * DDIM;
    for (int d = lane; d < DDIM; d += 32) {
        float xv = xr[d];
        const float4* r = (const float4*)(rw + (size_t)d * NEXP);
        float4 r0 = r[0], r1 = r[1];
        acc[0] += xv * r0.x; acc[1] += xv * r0.y;
        acc[2] += xv * r0.z; acc[3] += xv * r0.w;
        acc[4] += xv * r1.x; acc[5] += xv * r1.y;
        acc[6] += xv * r1.z; acc[7] += xv * r1.w;
    }
#pragma unroll
    for (int off = 16; off > 0; off >>= 1)
#pragma unroll
        for (int e = 0; e < NEXP; e++)
            acc[e] += __shfl_down_sync(0xffffffffu, acc[e], off);
    if (lane == 0) {
        int best = 0; float bv = acc[0];
#pragma unroll
        for (int e = 1; e < NEXP; e++)
            if (acc[e] > bv) { bv = acc[e]; best = e; }
        g_eid[t] = best;
        g_w[t]   = 1.f / (1.f + expf(-bv));
    }
}

__global__ void scatter_kernel() {
    int t = blockIdx.x * blockDim.x + threadIdx.x;
    if (t < T_TOK) {
        int e = g_eid[t];
        int p = atomicAdd(&g_cnt[e], 1);
        g_list[e * T_TOK + p] = t;
    }
}

// ================= gate+up GEMM =================
template<bool SHARED>
__global__ void __launch_bounds__(256)
gu_kernel(const float* __restrict__ x,
          const float* __restrict__ wgA,
          const float* __restrict__ wuA,
          float* __restrict__ hout) {
    int e   = SHARED ? 0 : blockIdx.z;
    int cnt = SHARED ? T_TOK : g_cnt[e];
    int m0  = blockIdx.y * 128;
    if (m0 >= cnt) return;
    int n0  = blockIdx.x * 64;
    const float* wg = wgA + (SHARED ? 0 : (size_t)e * DDIM * FDIM);
    const float* wu = wuA + (SHARED ? 0 : (size_t)e * DDIM * FDIM);

    extern __shared__ float sm[];
    __shared__ int toks[128];
    int tid = threadIdx.x;
    if (tid < 128) {
        int m = m0 + tid;
        toks[tid] = (m < cnt) ? (SHARED ? m : g_list[e * T_TOK + m]) : -1;
    }
    __syncthreads();

    uint32_t smb = smem_u32(sm);

    const float* asrc[4];
    int apred[4];
    uint32_t adst[4];
#pragma unroll
    for (int i = 0; i < 4; i++) {
        int s = tid + 256 * i;
        int row = s >> 3, chk = s & 7;
        int tk = toks[row];
        apred[i] = (tk >= 0) ? 16 : 0;
        asrc[i]  = x + ((tk >= 0) ? ((size_t)tk * DDIM + chk * 4) : 0);
        adst[i]  = (row * AS_STRIDE + chk * 4) * 4;
    }
    const float* bsrc[4];
    uint32_t bdst[4];
#pragma unroll
    for (int i = 0; i < 4; i++) {
        int s = tid + 256 * i;
        int row = s >> 5, chk = s & 31;
        const float* base = (chk < 16) ? (wg + n0 + chk * 4)
                                       : (wu + n0 + (chk - 16) * 4);
        bsrc[i] = base + (size_t)row * FDIM;
        bdst[i] = (A_TILE_FLTS + row * BS_STRIDE_GU + chk * 4) * 4;
    }

    auto load_stage = [&](int kc, int st) {
        uint32_t sb = smb + st * STAGE_GU * 4;
        int k0 = kc * 32;
#pragma unroll
        for (int i = 0; i < 4; i++) cpa16(sb + adst[i], asrc[i] + k0, apred[i]);
#pragma unroll
        for (int i = 0; i < 4; i++) cpa16(sb + bdst[i], bsrc[i] + (size_t)k0 * FDIM, 16);
        CP_COMMIT();
    };

    int wid = tid >> 5, lane = tid & 31;
    int wm = (wid >> 1) * 32;
    int wn = (wid & 1) * 32;
    int gr = lane >> 2, gc = lane & 3;

    float acc[2][8][4];
#pragma unroll
    for (int mt = 0; mt < 2; mt++)
#pragma unroll
        for (int nt = 0; nt < 8; nt++)
#pragma unroll
            for (int j = 0; j < 4; j++) acc[mt][nt][j] = 0.f;

    const int NKC = DDIM / 32;  // 64
    load_stage(0, 0);
    load_stage(1, 1);

    for (int kc = 0; kc < NKC; kc++) {
        CP_WAIT1();
        __syncthreads();
        if (kc + 2 < NKC) load_stage(kc + 2, (kc + 2) % NSTG);

        const float* As = sm + (kc % NSTG) * STAGE_GU;
        const float* Bs = As + A_TILE_FLTS;
#pragma unroll
        for (int ks = 0; ks < 2; ks++) {        // two k16 steps per 32-K chunk
            uint32_t a_hi[2][4], a_lo[2][4];
#pragma unroll
            for (int mt = 0; mt < 2; mt++) {
                const float* ap = As + (wm + mt * 16 + gr) * AS_STRIDE + ks * 16 + gc * 2;
                bf16_split2(*(const float2*)(ap),                     a_hi[mt][0], a_lo[mt][0]);
                bf16_split2(*(const float2*)(ap + 8 * AS_STRIDE),     a_hi[mt][1], a_lo[mt][1]);
                bf16_split2(*(const float2*)(ap + 8),                 a_hi[mt][2], a_lo[mt][2]);
                bf16_split2(*(const float2*)(ap + 8 * AS_STRIDE + 8), a_hi[mt][3], a_lo[mt][3]);
            }
#pragma unroll
            for (int nt = 0; nt < 8; nt++) {
                int col = (nt < 4) ? (wn + nt * 8) : (64 + wn + (nt - 4) * 8);
                const float* bp = Bs + (ks * 16 + gc * 2) * BS_STRIDE_GU + col + gr;
                uint32_t b_hi[2], b_lo[2];
                bf16_split2(make_float2(bp[0], bp[BS_STRIDE_GU]),                     b_hi[0], b_lo[0]);
                bf16_split2(make_float2(bp[8 * BS_STRIDE_GU], bp[9 * BS_STRIDE_GU]), b_hi[1], b_lo[1]);
#pragma unroll
                for (int mt = 0; mt < 2; mt++) {
                    MMA_BF16(acc[mt][nt], a_hi[mt], b_lo);
                    MMA_BF16(acc[mt][nt], a_lo[mt], b_hi);
                    MMA_BF16(acc[mt][nt], a_hi[mt], b_hi);
                }
            }
        }
        __syncthreads();
    }

#pragma unroll
    for (int mt = 0; mt < 2; mt++) {
#pragma unroll
        for (int half = 0; half < 2; half++) {
            int row = wm + mt * 16 + gr + half * 8;
            int tk = toks[row];
            if (tk < 0) continue;
            float* orow = hout + (size_t)tk * FDIM + n0 + wn;
#pragma unroll
            for (int nt = 0; nt < 4; nt++) {
                float gg0 = acc[mt][nt][half * 2 + 0];
                float gg1 = acc[mt][nt][half * 2 + 1];
                float uu0 = acc[mt][nt + 4][half * 2 + 0];
                float uu1 = acc[mt][nt + 4][half * 2 + 1];
                float2 v;
                v.x = silu_f(gg0) * uu0;
                v.y = silu_f(gg1) * uu1;
                *(float2*)(orow + nt * 8 + gc * 2) = v;
            }
        }
    }
}

// ================= down GEMM =================
template<bool SHARED>
__global__ void __launch_bounds__(256)
dn_kernel(const float* __restrict__ hin,
          const float* __restrict__ wdA,
          float* __restrict__ out) {
    int e   = SHARED ? 0 : blockIdx.z;
    int cnt = SHARED ? T_TOK : g_cnt[e];
    int m0  = blockIdx.y * 128;
    if (m0 >= cnt) return;
    int n0  = blockIdx.x * 64;
    const float* wd = wdA + (SHARED ? 0 : (size_t)e * FDIM * DDIM);

    extern __shared__ float sm[];
    __shared__ int toks[128];
    int tid = threadIdx.x;
    if (tid < 128) {
        int m = m0 + tid;
        toks[tid] = (m < cnt) ? (SHARED ? m : g_list[e * T_TOK + m]) : -1;
    }
    __syncthreads();

    uint32_t smb = smem_u32(sm);

    const float* asrc[4];
    int apred[4];
    uint32_t adst[4];
#pragma unroll
    for (int i = 0; i < 4; i++) {
        int s = tid + 256 * i;
        int row = s >> 3, chk = s & 7;
        int tk = toks[row];
        apred[i] = (tk >= 0) ? 16 : 0;
        asrc[i]  = hin + ((tk >= 0) ? ((size_t)tk * FDIM + chk * 4) : 0);
        adst[i]  = (row * AS_STRIDE + chk * 4) * 4;
    }
    const float* bsrc[2];
    uint32_t bdst[2];
#pragma unroll
    for (int i = 0; i < 2; i++) {
        int s = tid + 256 * i;
        int row = s >> 4, chk = s & 15;
        bsrc[i] = wd + (size_t)row * DDIM + n0 + chk * 4;
        bdst[i] = (A_TILE_FLTS + row * BS_STRIDE_DN + chk * 4) * 4;
    }

    auto load_stage = [&](int kc, int st) {
        uint32_t sb = smb + st * STAGE_DN * 4;
        int k0 = kc * 32;
#pragma unroll
        for (int i = 0; i < 4; i++) cpa16(sb + adst[i], asrc[i] + k0, apred[i]);
#pragma unroll
        for (int i = 0; i < 2; i++) cpa16(sb + bdst[i], bsrc[i] + (size_t)k0 * DDIM, 16);
        CP_COMMIT();
    };

    int wid = tid >> 5, lane = tid & 31;
    int wm = (wid >> 1) * 32;
    int wn = (wid & 1) * 32;
    int gr = lane >> 2, gc = lane & 3;

    float acc[2][4][4];
#pragma unroll
    for (int mt = 0; mt < 2; mt++)
#pragma unroll
        for (int nt = 0; nt < 4; nt++)
#pragma unroll
            for (int j = 0; j < 4; j++) acc[mt][nt][j] = 0.f;

    const int NKC = FDIM / 32;  // 128
    load_stage(0, 0);
    load_stage(1, 1);

    for (int kc = 0; kc < NKC; kc++) {
        CP_WAIT1();
        __syncthreads();
        if (kc + 2 < NKC) load_stage(kc + 2, (kc + 2) % NSTG);

        const float* As = sm + (kc % NSTG) * STAGE_DN;
        const float* Bs = As + A_TILE_FLTS;
#pragma unroll
        for (int ks = 0; ks < 2; ks++) {
            uint32_t a_hi[2][4], a_lo[2][4];
#pragma unroll
            for (int mt = 0; mt < 2; mt++) {
                const float* ap = As + (wm + mt * 16 + gr) * AS_STRIDE + ks * 16 + gc * 2;
                bf16_split2(*(const float2*)(ap),                     a_hi[mt][0], a_lo[mt][0]);
                bf16_split2(*(const float2*)(ap + 8 * AS_STRIDE),     a_hi[mt][1], a_lo[mt][1]);
                bf16_split2(*(const float2*)(ap + 8),                 a_hi[mt][2], a_lo[mt][2]);
                bf16_split2(*(const float2*)(ap + 8 * AS_STRIDE + 8), a_hi[mt][3], a_lo[mt][3]);
            }
#pragma unroll
            for (int nt = 0; nt < 4; nt++) {
                const float* bp = Bs + (ks * 16 + gc * 2) * BS_STRIDE_DN + wn + nt * 8 + gr;
                uint32_t b_hi[2], b_lo[2];
                bf16_split2(make_float2(bp[0], bp[BS_STRIDE_DN]),                     b_hi[0], b_lo[0]);
                bf16_split2(make_float2(bp[8 * BS_STRIDE_DN], bp[9 * BS_STRIDE_DN]), b_hi[1], b_lo[1]);
#pragma unroll
                for (int mt = 0; mt < 2; mt++) {
                    MMA_BF16(acc[mt][nt], a_hi[mt], b_lo);
                    MMA_BF16(acc[mt][nt], a_lo[mt], b_hi);
                    MMA_BF16(acc[mt][nt], a_hi[mt], b_hi);
                }
            }
        }
        __syncthreads();
    }

#pragma unroll
    for (int mt = 0; mt < 2; mt++) {
#pragma unroll
        for (int half = 0; half < 2; half++) {
            int row = wm + mt * 16 + gr + half * 8;
            int tk = toks[row];
            if (tk < 0) continue;
            float wt = SHARED ? 1.f : g_w[tk];
            float* orow = out + (size_t)tk * DDIM + n0 + wn;
#pragma unroll
            for (int nt = 0; nt < 4; nt++) {
                float2 v;
                v.x = wt * acc[mt][nt][half * 2 + 0];
                v.y = wt * acc[mt][nt][half * 2 + 1];
                float* op = orow + nt * 8 + gc * 2;
                if (SHARED) {
                    float2 p = *(float2*)op;
                    v.x += p.x; v.y += p.y;
                }
                *(float2*)op = v;
            }
        }
    }
}

// ================= host =================
extern "C" void kernel_launch(void* const* d_in, const int* in_sizes, int n_in,
                              void* d_out, int out_size) {
    const float* x   = (const float*)d_in[0];
    const float* rw  = (const float*)d_in[1];
    const float* wg  = (const float*)d_in[2];
    const float* wu  = (const float*)d_in[3];
    const float* wd  = (const float*)d_in[4];
    const float* wsg = (const float*)d_in[5];
    const float* wsu = (const float*)d_in[6];
    const float* wsd = (const float*)d_in[7];
    float* out = (float*)d_out;

    void *p_h = 0, *p_hs = 0;
    cudaGetSymbolAddress(&p_h, g_h);
    cudaGetSymbolAddress(&p_hs, g_hs);

    cudaFuncSetAttribute(gu_kernel<false>, cudaFuncAttributeMaxDynamicSharedMemorySize, SMEM_GU);
    cudaFuncSetAttribute(gu_kernel<true>,  cudaFuncAttributeMaxDynamicSharedMemorySize, SMEM_GU);
    cudaFuncSetAttribute(dn_kernel<false>, cudaFuncAttributeMaxDynamicSharedMemorySize, SMEM_DN);
    cudaFuncSetAttribute(dn_kernel<true>,  cudaFuncAttributeMaxDynamicSharedMemorySize, SMEM_DN);

    zero_counts<<<1, 32>>>();
    router_kernel<<<T_TOK / 8, dim3(32, 8)>>>(x, rw);
    scatter_kernel<<<T_TOK / 256, 256>>>();

    gu_kernel<false><<<dim3(FDIM / 64, T_TOK / 128, NEXP), 256, SMEM_GU>>>(x, wg, wu, (float*)p_h);
    dn_kernel<false><<<dim3(DDIM / 64, T_TOK / 128, NEXP), 256, SMEM_DN>>>((const float*)p_h, wd, out);

    gu_kernel<true><<<dim3(FDIM / 64, T_TOK / 128, 1), 256, SMEM_GU>>>(x, wsg, wsu, (float*)p_hs);
    dn_kernel<true><<<dim3(DDIM / 64, T_TOK / 128, 1), 256, SMEM_DN>>>((const float*)p_hs, wsd, out);
}